// round 2
// baseline (speedup 1.0000x reference)
#include <cuda_runtime.h>
#include <math.h>

#define VOCAB 32000
#define EMB 256
#define HID 256
#define BATCH 64
#define SEQT 2048

// Scratch: V[v][j] = sum_e emb[v][e]*W_ih[e][j] + b_ih[j] + b_hh[j]  (32 MB)
__device__ float g_V[VOCAB * HID];

// ---------------------------------------------------------------------------
// Kernel 1: vocab projection GEMM  [32000,256] x [256,256] + bias
// Block: 64 rows x 256 cols, 256 threads, thread j owns column j (64 accs).
// ---------------------------------------------------------------------------
__global__ void __launch_bounds__(256) vocab_proj_kernel(
    const float* __restrict__ emb, const float* __restrict__ W_ih,
    const float* __restrict__ b_ih, const float* __restrict__ b_hh)
{
    __shared__ float As[64][64];
    const int row0 = blockIdx.x * 64;
    const int j = threadIdx.x;

    const float bias = b_ih[j] + b_hh[j];

    float acc[64];
#pragma unroll
    for (int r = 0; r < 64; r++) acc[r] = 0.0f;

#pragma unroll 1
    for (int k0 = 0; k0 < EMB; k0 += 64) {
        __syncthreads();
        // Load A tile: 64 rows x 64 k's, coalesced
#pragma unroll
        for (int i = threadIdx.x; i < 64 * 64; i += 256) {
            int r = i >> 6, kk = i & 63;
            As[r][kk] = emb[(size_t)(row0 + r) * EMB + (k0 + kk)];
        }
        __syncthreads();

#pragma unroll 1
        for (int kk = 0; kk < 64; kk += 4) {
            // W column loads, coalesced across j; L2-resident after first wave
            float w0 = W_ih[(size_t)(k0 + kk + 0) * HID + j];
            float w1 = W_ih[(size_t)(k0 + kk + 1) * HID + j];
            float w2 = W_ih[(size_t)(k0 + kk + 2) * HID + j];
            float w3 = W_ih[(size_t)(k0 + kk + 3) * HID + j];
#pragma unroll
            for (int r = 0; r < 64; r++) {
                float4 a = *(const float4*)&As[r][kk];   // broadcast LDS.128
                acc[r] = fmaf(a.x, w0, acc[r]);
                acc[r] = fmaf(a.y, w1, acc[r]);
                acc[r] = fmaf(a.z, w2, acc[r]);
                acc[r] = fmaf(a.w, w3, acc[r]);
            }
        }
    }

#pragma unroll
    for (int r = 0; r < 64; r++)
        g_V[(size_t)(row0 + r) * HID + j] = acc[r] + bias;
}

// ---------------------------------------------------------------------------
// Kernel 2: recurrence. One persistent CTA per batch element (64 CTAs).
// 512 threads: thread t = (j = t&255, half = t>>8); thread computes the
// partial dot for column j over k in [half*128, half*128+128).
// W_hh split: first 64 k's of each half in registers (512*64 = full matrix
// half), remaining 64 k's in SMEM fp32 (128 KB). FFMA-bound: ~1024 cyc/step.
// ---------------------------------------------------------------------------
__global__ void __launch_bounds__(512) rnn_kernel(
    const int* __restrict__ source, const float* __restrict__ W_hh,
    float* __restrict__ out)
{
    extern __shared__ float sm[];
    float* Wsm     = sm;                    // 128 * 256 floats (128 KB)
    float* hs      = sm + 128 * 256;        // 256 floats
    float* partial = hs + 256;              // 512 floats
    int*   src_s   = (int*)(partial + 512); // 2048 ints

    const int t    = threadIdx.x;
    const int j    = t & 255;
    const int half = t >> 8;
    const int b    = blockIdx.x;

    // Preload this chain's source indices (8 KB)
    for (int i = t; i < SEQT; i += 512) src_s[i] = source[b * SEQT + i];

    // SMEM half of W_hh: rows (half*128 + 64 .. half*128 + 127) stored at
    // Wsm[(half*64 + kk)*256 + col]
    for (int idx = t; idx < 128 * 256; idx += 512) {
        int r   = idx >> 8;     // 0..127
        int col = idx & 255;
        int hh  = r >> 6;
        int kk  = r & 63;
        Wsm[idx] = W_hh[(size_t)(hh * 128 + 64 + kk) * HID + col];
    }

    // Register half of W_hh: rows (half*128 .. half*128 + 63), column j
    float wreg[64];
#pragma unroll
    for (int kk = 0; kk < 64; kk++)
        wreg[kk] = W_hh[(size_t)(half * 128 + kk) * HID + j];

    if (t < 256) hs[t] = 0.0f;
    __syncthreads();

    const int kb = half * 128;
    const float* hs0 = hs + kb;        // h for register part
    const float* hs1 = hs + kb + 64;   // h for smem part
    const float* Wp  = Wsm + (half * 64) * 256 + j;

    float hval = 0.0f;

#pragma unroll 1
    for (int step = 0; step < SEQT; step++) {
        // Issue the V gather early; consumed ~1000 cycles later (L2 latency hidden)
        float xv = 0.0f;
        if (t < 256) xv = g_V[(size_t)src_s[step] * HID + t];

        float p = 0.0f;
        // Register-resident W part
#pragma unroll
        for (int kk = 0; kk < 64; kk += 4) {
            float4 hv = *(const float4*)(hs0 + kk);   // broadcast LDS.128
            p = fmaf(hv.x, wreg[kk + 0], p);
            p = fmaf(hv.y, wreg[kk + 1], p);
            p = fmaf(hv.z, wreg[kk + 2], p);
            p = fmaf(hv.w, wreg[kk + 3], p);
        }
        // SMEM-resident W part (stride-1 across lanes -> conflict-free)
#pragma unroll
        for (int kk = 0; kk < 64; kk += 4) {
            float4 hv = *(const float4*)(hs1 + kk);
            p = fmaf(hv.x, Wp[(kk + 0) * 256], p);
            p = fmaf(hv.y, Wp[(kk + 1) * 256], p);
            p = fmaf(hv.z, Wp[(kk + 2) * 256], p);
            p = fmaf(hv.w, Wp[(kk + 3) * 256], p);
        }
        partial[t] = p;
        __syncthreads();

        if (t < 256) {
            hval = tanhf(xv + partial[t] + partial[t + 256]);
            hs[t] = hval;
        }
        __syncthreads();
    }

    if (t < 256) out[b * HID + t] = hval;
}

// ---------------------------------------------------------------------------
extern "C" void kernel_launch(void* const* d_in, const int* in_sizes, int n_in,
                              void* d_out, int out_size)
{
    const int*   source    = (const int*)d_in[0];
    const float* embedding = (const float*)d_in[1];
    const float* W_ih      = (const float*)d_in[2];
    const float* W_hh      = (const float*)d_in[3];
    const float* b_ih      = (const float*)d_in[4];
    const float* b_hh      = (const float*)d_in[5];
    float* out = (float*)d_out;

    const int smem_bytes = (128 * 256 + 256 + 512) * 4 + SEQT * 4;  // 142336 B
    cudaFuncSetAttribute(rnn_kernel,
                         cudaFuncAttributeMaxDynamicSharedMemorySize,
                         smem_bytes);

    vocab_proj_kernel<<<VOCAB / 64, 256>>>(embedding, W_ih, b_ih, b_hh);
    rnn_kernel<<<BATCH, 512, smem_bytes>>>(source, W_hh, out);
}

// round 3
// speedup vs baseline: 2.5197x; 2.5197x over previous
#include <cuda_runtime.h>
#include <math.h>
#include <stdint.h>

#define VOCAB 32000
#define EMB 256
#define HID 256
#define BATCH 64
#define SEQT 2048

// Scratch: V[v][j] = sum_e emb[v][e]*W_ih[e][j] + b_ih[j] + b_hh[j]  (32 MB, L2-resident)
__device__ float g_V[VOCAB * HID];

// ---------------------------------------------------------------------------
// f32x2 packed helpers (PTX-only; ptxas won't auto-fuse)
// ---------------------------------------------------------------------------
__device__ __forceinline__ unsigned long long pack2(float lo, float hi) {
    unsigned long long r;
    asm("mov.b64 %0, {%1, %2};" : "=l"(r) : "f"(lo), "f"(hi));
    return r;
}
__device__ __forceinline__ void fma2(unsigned long long& acc,
                                     unsigned long long a, unsigned long long b) {
    asm("fma.rn.f32x2 %0, %1, %2, %0;" : "+l"(acc) : "l"(a), "l"(b));
}
__device__ __forceinline__ unsigned long long add2(unsigned long long a,
                                                   unsigned long long b) {
    unsigned long long r;
    asm("add.rn.f32x2 %0, %1, %2;" : "=l"(r) : "l"(a), "l"(b));
    return r;
}
__device__ __forceinline__ void unpack2(unsigned long long v, float& lo, float& hi) {
    asm("mov.b64 {%0, %1}, %2;" : "=f"(lo), "=f"(hi) : "l"(v));
}

// Cluster helpers
__device__ __forceinline__ uint32_t smem_u32(const void* p) {
    uint32_t a;
    asm("{ .reg .u64 t; cvta.to.shared.u64 t, %1; cvt.u32.u64 %0, t; }"
        : "=r"(a) : "l"(p));
    return a;
}
__device__ __forceinline__ uint32_t mapa_peer(uint32_t addr, uint32_t rank) {
    uint32_t r;
    asm("mapa.shared::cluster.u32 %0, %1, %2;" : "=r"(r) : "r"(addr), "r"(rank));
    return r;
}
__device__ __forceinline__ void st_cluster_f32(uint32_t addr, float v) {
    asm volatile("st.shared::cluster.f32 [%0], %1;" :: "r"(addr), "f"(v) : "memory");
}
#define CLUSTER_SYNC() do { \
    asm volatile("barrier.cluster.arrive.aligned;" ::: "memory"); \
    asm volatile("barrier.cluster.wait.aligned;" ::: "memory"); \
} while (0)

// ---------------------------------------------------------------------------
// Kernel 1: vocab projection GEMM  [32000,256] x [256,256] + bias  (f32x2)
// Block: 64 rows x 256 cols, 256 threads. Thread j owns column j, 64 row-accs
// packed as 32 f32x2. A tile stored transposed so row-pairs are contiguous.
// ---------------------------------------------------------------------------
__global__ void __launch_bounds__(256) vocab_proj_kernel(
    const float* __restrict__ emb, const float* __restrict__ W_ih,
    const float* __restrict__ b_ih, const float* __restrict__ b_hh)
{
    __shared__ float As_T[32][68];  // [kk][row], padded: 68*4 B row stride (16B aligned)
    const int row0 = blockIdx.x * 64;
    const int j = threadIdx.x;

    const float bias = b_ih[j] + b_hh[j];

    unsigned long long acc[32];  // acc[p] = rows (2p, 2p+1)
#pragma unroll
    for (int p = 0; p < 32; p++) acc[p] = 0ull;

#pragma unroll 1
    for (int k0 = 0; k0 < EMB; k0 += 32) {
        __syncthreads();
        // Load tile transposed: As_T[kk][r] = emb[(row0+r)*EMB + k0+kk]; coalesced
#pragma unroll
        for (int it = 0; it < 8; it++) {
            int idx = it * 256 + threadIdx.x;
            int r  = idx >> 5;
            int kk = idx & 31;
            As_T[kk][r] = emb[(size_t)(row0 + r) * EMB + (k0 + kk)];
        }
        __syncthreads();

        // Preload W column slice into registers (high MLP, L2-hot)
        float wt[32];
#pragma unroll
        for (int kk = 0; kk < 32; kk++)
            wt[kk] = W_ih[(size_t)(k0 + kk) * HID + j];

#pragma unroll
        for (int kk = 0; kk < 32; kk++) {
            unsigned long long ws = pack2(wt[kk], wt[kk]);
#pragma unroll
            for (int rp2 = 0; rp2 < 16; rp2++) {
                ulonglong2 av = *(const ulonglong2*)&As_T[kk][4 * rp2];  // rows 4rp2..4rp2+3
                fma2(acc[2 * rp2 + 0], av.x, ws);
                fma2(acc[2 * rp2 + 1], av.y, ws);
            }
        }
    }

#pragma unroll
    for (int p = 0; p < 32; p++) {
        float lo, hi;
        unpack2(acc[p], lo, hi);
        g_V[(size_t)(row0 + 2 * p + 0) * HID + j] = lo + bias;
        g_V[(size_t)(row0 + 2 * p + 1) * HID + j] = hi + bias;
    }
}

// ---------------------------------------------------------------------------
// Kernel 2: recurrence. 2-CTA cluster per batch element (128 CTAs, 1 wave).
// CTA owns output columns [rank*128, rank*128+128). 256 threads:
//   col = t & 127 (local column), khalf = t >> 7 -> k in [khalf*128, +128).
// W_hh column slice fully register-resident: 128 fp32 = 64 f32x2 per thread.
// h double-buffered in SMEM; producers write h to own + peer SMEM each step;
// one barrier.cluster per step gives ordering (release/acquire).
// ---------------------------------------------------------------------------
__global__ void __launch_bounds__(256, 1) __cluster_dims__(2, 1, 1)
rnn_kernel(const int* __restrict__ source, const float* __restrict__ W_hh,
           float* __restrict__ out)
{
    __shared__ float hs[2][256];
    __shared__ float partial[256];
    __shared__ int   src_s[SEQT];

    const int t = threadIdx.x;
    const int col = t & 127;
    const int khalf = t >> 7;
    const int k0 = khalf * 128;
    const int b = blockIdx.x >> 1;

    uint32_t rank;
    asm("mov.u32 %0, %%cluster_ctarank;" : "=r"(rank));

    const int jout = (int)rank * 128 + col;  // global output column of thread t (t<128)

    // Preload source indices for this batch element
    for (int i = t; i < SEQT; i += 256) src_s[i] = source[b * SEQT + i];

    // W_hh[k0..k0+127][j] into registers, packed over k pairs
    unsigned long long w[64];
    {
        const int j = (int)rank * 128 + col;  // the column this thread's MACs serve
#pragma unroll
        for (int i = 0; i < 64; i++)
            w[i] = pack2(W_hh[(size_t)(k0 + 2 * i + 0) * HID + j],
                         W_hh[(size_t)(k0 + 2 * i + 1) * HID + j]);
    }

    if (t < 256) hs[0][t] = 0.0f;

    // Peer SMEM addresses for this thread's output slot, both buffers
    uint32_t peer_slot[2];
    {
        uint32_t a0 = smem_u32(&hs[0][jout]);
        uint32_t a1 = smem_u32(&hs[1][jout]);
        peer_slot[0] = mapa_peer(a0, rank ^ 1u);
        peer_slot[1] = mapa_peer(a1, rank ^ 1u);
    }

    __syncthreads();
    CLUSTER_SYNC();

    float hval = 0.0f;

#pragma unroll 1
    for (int step = 0; step < SEQT; step++) {
        const int cur = step & 1;
        const int nxt = cur ^ 1;

        // Prefetch x-projection value (L2 gather; consumed after the FMA block)
        float xv = 0.0f;
        if (t < 128) xv = g_V[(size_t)src_s[step] * HID + jout];

        const float* hp = &hs[cur][k0];
        unsigned long long a0 = 0, a1 = 0, a2 = 0, a3 = 0;
        unsigned long long b0 = 0, b1 = 0, b2 = 0, b3 = 0;
#pragma unroll
        for (int q = 0; q < 32; q += 4) {
            ulonglong2 h0 = *(const ulonglong2*)(hp + 4 * (q + 0));
            ulonglong2 h1 = *(const ulonglong2*)(hp + 4 * (q + 1));
            ulonglong2 h2 = *(const ulonglong2*)(hp + 4 * (q + 2));
            ulonglong2 h3 = *(const ulonglong2*)(hp + 4 * (q + 3));
            fma2(a0, h0.x, w[2 * q + 0]); fma2(b0, h0.y, w[2 * q + 1]);
            fma2(a1, h1.x, w[2 * q + 2]); fma2(b1, h1.y, w[2 * q + 3]);
            fma2(a2, h2.x, w[2 * q + 4]); fma2(b2, h2.y, w[2 * q + 5]);
            fma2(a3, h3.x, w[2 * q + 6]); fma2(b3, h3.y, w[2 * q + 7]);
        }
        unsigned long long s = add2(add2(add2(a0, a1), add2(a2, a3)),
                                    add2(add2(b0, b1), add2(b2, b3)));
        float lo, hi;
        unpack2(s, lo, hi);
        partial[t] = lo + hi;
        __syncthreads();

        if (t < 128) {
            float pre = xv + partial[t] + partial[t + 128];
            // tanh(x) = 1 - 2/(exp(2x)+1); __expf/__fdividef saturate correctly
            float e = __expf(2.0f * pre);
            hval = 1.0f - __fdividef(2.0f, e + 1.0f);
            hs[nxt][jout] = hval;                 // local copy
            st_cluster_f32(peer_slot[nxt], hval); // peer copy (512B/CTA)
        }

        CLUSTER_SYNC();  // orders remote h stores + recycles partial/hs buffers
    }

    if (t < 128) out[b * HID + jout] = hval;
}

// ---------------------------------------------------------------------------
extern "C" void kernel_launch(void* const* d_in, const int* in_sizes, int n_in,
                              void* d_out, int out_size)
{
    const int*   source    = (const int*)d_in[0];
    const float* embedding = (const float*)d_in[1];
    const float* W_ih      = (const float*)d_in[2];
    const float* W_hh      = (const float*)d_in[3];
    const float* b_ih      = (const float*)d_in[4];
    const float* b_hh      = (const float*)d_in[5];
    float* out = (float*)d_out;

    vocab_proj_kernel<<<VOCAB / 64, 256>>>(embedding, W_ih, b_ih, b_hh);
    rnn_kernel<<<BATCH * 2, 256>>>(source, W_hh, out);
}

// round 4
// speedup vs baseline: 2.5851x; 1.0260x over previous
#include <cuda_runtime.h>
#include <math.h>
#include <stdint.h>

#define VOCAB 32000
#define EMB 256
#define HID 256
#define BATCH 64
#define SEQT 2048

// Scratch: V[v][j] = sum_e emb[v][e]*W_ih[e][j] + b_ih[j] + b_hh[j]  (32 MB, L2-resident)
__device__ float g_V[VOCAB * HID];

// ---------------------------------------------------------------------------
// f32x2 packed helpers (PTX-only; ptxas won't auto-fuse)
// ---------------------------------------------------------------------------
__device__ __forceinline__ unsigned long long pack2(float lo, float hi) {
    unsigned long long r;
    asm("mov.b64 %0, {%1, %2};" : "=l"(r) : "f"(lo), "f"(hi));
    return r;
}
__device__ __forceinline__ void fma2(unsigned long long& acc,
                                     unsigned long long a, unsigned long long b) {
    asm("fma.rn.f32x2 %0, %1, %2, %0;" : "+l"(acc) : "l"(a), "l"(b));
}
__device__ __forceinline__ unsigned long long add2(unsigned long long a,
                                                   unsigned long long b) {
    unsigned long long r;
    asm("add.rn.f32x2 %0, %1, %2;" : "=l"(r) : "l"(a), "l"(b));
    return r;
}
__device__ __forceinline__ void unpack2(unsigned long long v, float& lo, float& hi) {
    asm("mov.b64 {%0, %1}, %2;" : "=f"(lo), "=f"(hi) : "l"(v));
}

// Cluster helpers
__device__ __forceinline__ uint32_t smem_u32(const void* p) {
    uint32_t a;
    asm("{ .reg .u64 t; cvta.to.shared.u64 t, %1; cvt.u32.u64 %0, t; }"
        : "=r"(a) : "l"(p));
    return a;
}
__device__ __forceinline__ uint32_t mapa_peer(uint32_t addr, uint32_t rank) {
    uint32_t r;
    asm("mapa.shared::cluster.u32 %0, %1, %2;" : "=r"(r) : "r"(addr), "r"(rank));
    return r;
}
__device__ __forceinline__ void st_cluster_f32(uint32_t addr, float v) {
    asm volatile("st.shared::cluster.f32 [%0], %1;" :: "r"(addr), "f"(v) : "memory");
}
__device__ __forceinline__ void mbar_init(uint32_t addr, uint32_t count) {
    asm volatile("mbarrier.init.shared.b64 [%0], %1;" :: "r"(addr), "r"(count) : "memory");
}
__device__ __forceinline__ void mbar_arrive_cluster(uint32_t remote_addr) {
    asm volatile("mbarrier.arrive.release.cluster.shared::cluster.b64 _, [%0];"
                 :: "r"(remote_addr) : "memory");
}
__device__ __forceinline__ void mbar_wait_parity(uint32_t addr, uint32_t parity) {
    uint32_t done;
    asm volatile(
        "{\n\t"
        ".reg .pred p;\n\t"
        "mbarrier.try_wait.parity.acquire.cluster.shared::cta.b64 p, [%1], %2;\n\t"
        "selp.b32 %0, 1, 0, p;\n\t"
        "}" : "=r"(done) : "r"(addr), "r"(parity) : "memory");
    if (!done) {
        asm volatile(
            "{\n\t"
            ".reg .pred P1;\n\t"
            "WL_%=:\n\t"
            "mbarrier.try_wait.parity.acquire.cluster.shared::cta.b64 P1, [%0], %1, 0x989680;\n\t"
            "@P1 bra.uni WD_%=;\n\t"
            "bra.uni WL_%=;\n\t"
            "WD_%=:\n\t"
            "}" :: "r"(addr), "r"(parity) : "memory");
    }
}
#define CLUSTER_SYNC() do { \
    asm volatile("barrier.cluster.arrive.aligned;" ::: "memory"); \
    asm volatile("barrier.cluster.wait.aligned;" ::: "memory"); \
} while (0)

// ---------------------------------------------------------------------------
// Kernel 1: vocab projection GEMM  [32000,256] x [256,256] + bias  (f32x2)
// ---------------------------------------------------------------------------
__global__ void __launch_bounds__(256) vocab_proj_kernel(
    const float* __restrict__ emb, const float* __restrict__ W_ih,
    const float* __restrict__ b_ih, const float* __restrict__ b_hh)
{
    __shared__ float As_T[32][68];
    const int row0 = blockIdx.x * 64;
    const int j = threadIdx.x;

    const float bias = b_ih[j] + b_hh[j];

    unsigned long long acc[32];
#pragma unroll
    for (int p = 0; p < 32; p++) acc[p] = 0ull;

#pragma unroll 1
    for (int k0 = 0; k0 < EMB; k0 += 32) {
        __syncthreads();
#pragma unroll
        for (int it = 0; it < 8; it++) {
            int idx = it * 256 + threadIdx.x;
            int r  = idx >> 5;
            int kk = idx & 31;
            As_T[kk][r] = emb[(size_t)(row0 + r) * EMB + (k0 + kk)];
        }
        __syncthreads();

        float wt[32];
#pragma unroll
        for (int kk = 0; kk < 32; kk++)
            wt[kk] = W_ih[(size_t)(k0 + kk) * HID + j];

#pragma unroll
        for (int kk = 0; kk < 32; kk++) {
            unsigned long long ws = pack2(wt[kk], wt[kk]);
#pragma unroll
            for (int rp2 = 0; rp2 < 16; rp2++) {
                ulonglong2 av = *(const ulonglong2*)&As_T[kk][4 * rp2];
                fma2(acc[2 * rp2 + 0], av.x, ws);
                fma2(acc[2 * rp2 + 1], av.y, ws);
            }
        }
    }

#pragma unroll
    for (int p = 0; p < 32; p++) {
        float lo, hi;
        unpack2(acc[p], lo, hi);
        g_V[(size_t)(row0 + 2 * p + 0) * HID + j] = lo + bias;
        g_V[(size_t)(row0 + 2 * p + 1) * HID + j] = hi + bias;
    }
}

// ---------------------------------------------------------------------------
// Kernel 2: recurrence. 2-CTA cluster per chain, mbarrier handshake.
// Thread t = (col = t&127, khalf = t>>7). W slice register-resident (64 f32x2).
// Warps with khalf == rank  : their h half is produced locally -> no wait.
// Warps with khalf == rank^1: wait on mbar[cur] for the peer's h half.
// ---------------------------------------------------------------------------
__global__ void __launch_bounds__(256, 1) __cluster_dims__(2, 1, 1)
rnn_kernel(const int* __restrict__ source, const float* __restrict__ W_hh,
           float* __restrict__ out)
{
    __shared__ float hs[2][256];
    __shared__ float partial[256];
    __shared__ int   src_s[SEQT];
    __shared__ __align__(8) unsigned long long mbar[2];

    const int t = threadIdx.x;
    const int col = t & 127;
    const int khalf = t >> 7;
    const int k0 = khalf * 128;
    const int b = blockIdx.x >> 1;

    uint32_t rank;
    asm("mov.u32 %0, %%cluster_ctarank;" : "=r"(rank));

    const int jout = (int)rank * 128 + col;
    const bool remote_grp = (khalf == (int)(rank ^ 1u));  // warp-uniform

    for (int i = t; i < SEQT; i += 256) src_s[i] = source[b * SEQT + i];

    unsigned long long w[64];
#pragma unroll
    for (int i = 0; i < 64; i++)
        w[i] = pack2(W_hh[(size_t)(k0 + 2 * i + 0) * HID + jout],
                     W_hh[(size_t)(k0 + 2 * i + 1) * HID + jout]);

    hs[0][t] = 0.0f;
    hs[1][t] = 0.0f;
    if (t == 0) { mbar_init(smem_u32(&mbar[0]), 1); mbar_init(smem_u32(&mbar[1]), 1); }

    // Peer addresses
    uint32_t peer_slot[2], peer_mbar[2];
    {
        peer_slot[0] = mapa_peer(smem_u32(&hs[0][jout]), rank ^ 1u);
        peer_slot[1] = mapa_peer(smem_u32(&hs[1][jout]), rank ^ 1u);
        peer_mbar[0] = mapa_peer(smem_u32(&mbar[0]), rank ^ 1u);
        peer_mbar[1] = mapa_peer(smem_u32(&mbar[1]), rank ^ 1u);
    }
    const uint32_t mbar_local[2] = { smem_u32(&mbar[0]), smem_u32(&mbar[1]) };

    __syncthreads();
    CLUSTER_SYNC();  // mbarriers + hs init visible cluster-wide

    float hval = 0.0f;

#pragma unroll 1
    for (int step = 0; step < SEQT; step++) {
        const int cur = step & 1;
        const int nxt = cur ^ 1;

        // Prefetch x-projection value (L2 gather; consumed after fma block)
        float xv = 0.0f;
        if (t < 128) xv = g_V[(size_t)src_s[step] * HID + jout];

        // Remote-half warps wait for the peer's h; local-half warps proceed.
        if (remote_grp && step > 0)
            mbar_wait_parity(mbar_local[cur], ((uint32_t)(step - 1) >> 1) & 1u);

        const float* hp = &hs[cur][k0];
        unsigned long long a0 = 0, a1 = 0, a2 = 0, a3 = 0;
        unsigned long long b0 = 0, b1 = 0, b2 = 0, b3 = 0;
#pragma unroll
        for (int q = 0; q < 32; q += 4) {
            ulonglong2 h0 = *(const ulonglong2*)(hp + 4 * (q + 0));
            ulonglong2 h1 = *(const ulonglong2*)(hp + 4 * (q + 1));
            ulonglong2 h2 = *(const ulonglong2*)(hp + 4 * (q + 2));
            ulonglong2 h3 = *(const ulonglong2*)(hp + 4 * (q + 3));
            fma2(a0, h0.x, w[2 * q + 0]); fma2(b0, h0.y, w[2 * q + 1]);
            fma2(a1, h1.x, w[2 * q + 2]); fma2(b1, h1.y, w[2 * q + 3]);
            fma2(a2, h2.x, w[2 * q + 4]); fma2(b2, h2.y, w[2 * q + 5]);
            fma2(a3, h3.x, w[2 * q + 6]); fma2(b3, h3.y, w[2 * q + 7]);
        }
        unsigned long long s = add2(add2(add2(a0, a1), add2(a2, a3)),
                                    add2(add2(b0, b1), add2(b2, b3)));
        float lo, hi;
        unpack2(s, lo, hi);
        partial[t] = lo + hi;
        __syncthreads();  // bar#1: partial ready; also orders all hs[cur] reads

        if (t < 128) {
            float pre = xv + partial[t] + partial[t + 128];
            float e = __expf(2.0f * pre);
            hval = 1.0f - __fdividef(2.0f, e + 1.0f);
            hs[nxt][jout] = hval;                 // local copy
            st_cluster_f32(peer_slot[nxt], hval); // peer copy (512 B)
        }
        __syncthreads();  // bar#2: local h visible; remote stores program-ordered
                          // before the single release-arrive below

        if (t == 0) mbar_arrive_cluster(peer_mbar[nxt]);
    }

    if (t < 128) out[b * HID + jout] = hval;

    CLUSTER_SYNC();  // peer stores/arrives targeting our SMEM must land before exit
}

// ---------------------------------------------------------------------------
extern "C" void kernel_launch(void* const* d_in, const int* in_sizes, int n_in,
                              void* d_out, int out_size)
{
    const int*   source    = (const int*)d_in[0];
    const float* embedding = (const float*)d_in[1];
    const float* W_ih      = (const float*)d_in[2];
    const float* W_hh      = (const float*)d_in[3];
    const float* b_ih      = (const float*)d_in[4];
    const float* b_hh      = (const float*)d_in[5];
    float* out = (float*)d_out;

    vocab_proj_kernel<<<VOCAB / 64, 256>>>(embedding, W_ih, b_ih, b_hh);
    rnn_kernel<<<BATCH * 2, 256>>>(source, W_hh, out);
}

// round 5
// speedup vs baseline: 3.9968x; 1.5461x over previous
#include <cuda_runtime.h>
#include <math.h>
#include <stdint.h>

#define VOCAB 32000
#define EMB 256
#define HID 256
#define BATCH 64
#define SEQT 2048

// Scratch: V[v][j] = sum_e emb[v][e]*W_ih[e][j] + b_ih[j] + b_hh[j]  (32 MB, L2-resident)
__device__ float g_V[VOCAB * HID];

// ---------------------------------------------------------------------------
// f32x2 packed helpers (PTX-only; ptxas won't auto-fuse)
// ---------------------------------------------------------------------------
__device__ __forceinline__ unsigned long long pack2(float lo, float hi) {
    unsigned long long r;
    asm("mov.b64 %0, {%1, %2};" : "=l"(r) : "f"(lo), "f"(hi));
    return r;
}
__device__ __forceinline__ void fma2(unsigned long long& acc,
                                     unsigned long long a, unsigned long long b) {
    asm("fma.rn.f32x2 %0, %1, %2, %0;" : "+l"(acc) : "l"(a), "l"(b));
}
__device__ __forceinline__ unsigned long long add2(unsigned long long a,
                                                   unsigned long long b) {
    unsigned long long r;
    asm("add.rn.f32x2 %0, %1, %2;" : "=l"(r) : "l"(a), "l"(b));
    return r;
}
__device__ __forceinline__ void unpack2(unsigned long long v, float& lo, float& hi) {
    asm("mov.b64 {%0, %1}, %2;" : "=f"(lo), "=f"(hi) : "l"(v));
}

// Cluster / mbarrier helpers
__device__ __forceinline__ uint32_t smem_u32(const void* p) {
    uint32_t a;
    asm("{ .reg .u64 t; cvta.to.shared.u64 t, %1; cvt.u32.u64 %0, t; }"
        : "=r"(a) : "l"(p));
    return a;
}
__device__ __forceinline__ uint32_t mapa_peer(uint32_t addr, uint32_t rank) {
    uint32_t r;
    asm("mapa.shared::cluster.u32 %0, %1, %2;" : "=r"(r) : "r"(addr), "r"(rank));
    return r;
}
__device__ __forceinline__ void mbar_init(uint32_t addr, uint32_t count) {
    asm volatile("mbarrier.init.shared.b64 [%0], %1;" :: "r"(addr), "r"(count) : "memory");
}
__device__ __forceinline__ void mbar_expect_tx(uint32_t addr, uint32_t bytes) {
    asm volatile("mbarrier.arrive.expect_tx.shared.b64 _, [%0], %1;"
                 :: "r"(addr), "r"(bytes) : "memory");
}
// Remote store fused with peer-mbar tx completion (data + signal in one op)
__device__ __forceinline__ void st_async_f32(uint32_t remote_addr, float v,
                                             uint32_t remote_mbar) {
    asm volatile(
        "st.async.shared::cluster.mbarrier::complete_tx::bytes.b32 [%0], %1, [%2];"
        :: "r"(remote_addr), "r"(__float_as_int(v)), "r"(remote_mbar) : "memory");
}
__device__ __forceinline__ void mbar_wait_parity(uint32_t addr, uint32_t parity) {
    uint32_t done;
    asm volatile(
        "{\n\t"
        ".reg .pred p;\n\t"
        "mbarrier.try_wait.parity.acquire.cluster.shared::cta.b64 p, [%1], %2;\n\t"
        "selp.b32 %0, 1, 0, p;\n\t"
        "}" : "=r"(done) : "r"(addr), "r"(parity) : "memory");
    if (!done) {
        asm volatile(
            "{\n\t"
            ".reg .pred P1;\n\t"
            "WL_%=:\n\t"
            "mbarrier.try_wait.parity.acquire.cluster.shared::cta.b64 P1, [%0], %1, 0x989680;\n\t"
            "@P1 bra.uni WD_%=;\n\t"
            "bra.uni WL_%=;\n\t"
            "WD_%=:\n\t"
            "}" :: "r"(addr), "r"(parity) : "memory");
    }
}
#define CLUSTER_SYNC() do { \
    asm volatile("barrier.cluster.arrive.aligned;" ::: "memory"); \
    asm volatile("barrier.cluster.wait.aligned;" ::: "memory"); \
} while (0)

// ---------------------------------------------------------------------------
// Kernel 1: vocab projection GEMM  [32000,256] x [256,256] + bias  (f32x2)
// ---------------------------------------------------------------------------
__global__ void __launch_bounds__(256) vocab_proj_kernel(
    const float* __restrict__ emb, const float* __restrict__ W_ih,
    const float* __restrict__ b_ih, const float* __restrict__ b_hh)
{
    __shared__ float As_T[32][68];
    const int row0 = blockIdx.x * 64;
    const int j = threadIdx.x;

    const float bias = b_ih[j] + b_hh[j];

    unsigned long long acc[32];
#pragma unroll
    for (int p = 0; p < 32; p++) acc[p] = 0ull;

#pragma unroll 1
    for (int k0 = 0; k0 < EMB; k0 += 32) {
        __syncthreads();
#pragma unroll
        for (int it = 0; it < 8; it++) {
            int idx = it * 256 + threadIdx.x;
            int r  = idx >> 5;
            int kk = idx & 31;
            As_T[kk][r] = emb[(size_t)(row0 + r) * EMB + (k0 + kk)];
        }
        __syncthreads();

        float wt[32];
#pragma unroll
        for (int kk = 0; kk < 32; kk++)
            wt[kk] = W_ih[(size_t)(k0 + kk) * HID + j];

#pragma unroll
        for (int kk = 0; kk < 32; kk++) {
            unsigned long long ws = pack2(wt[kk], wt[kk]);
#pragma unroll
            for (int rp2 = 0; rp2 < 16; rp2++) {
                ulonglong2 av = *(const ulonglong2*)&As_T[kk][4 * rp2];
                fma2(acc[2 * rp2 + 0], av.x, ws);
                fma2(acc[2 * rp2 + 1], av.y, ws);
            }
        }
    }

#pragma unroll
    for (int p = 0; p < 32; p++) {
        float lo, hi;
        unpack2(acc[p], lo, hi);
        g_V[(size_t)(row0 + 2 * p + 0) * HID + j] = lo + bias;
        g_V[(size_t)(row0 + 2 * p + 1) * HID + j] = hi + bias;
    }
}

// ---------------------------------------------------------------------------
// Kernel 2: recurrence. 2-CTA cluster per chain, st.async handshake.
// Warp w: pair p = w&3 (cols p*32..p*32+31, one col per lane), kh = w>>2.
// Each SMSP holds exactly one local-half and one remote-half warp.
//  local warp  (kh == rank):   FMA over own-produced h half -> partial[col]
//  remote warp (kh == rank^1): wait mbar, FMA over peer h half, merge via
//                              named bar, tanh, STS local + st.async to peer.
// One __syncthreads per step (local h visibility + buffer recycle).
// ---------------------------------------------------------------------------
__global__ void __launch_bounds__(256, 1) __cluster_dims__(2, 1, 1)
rnn_kernel(const int* __restrict__ source, const float* __restrict__ W_hh,
           float* __restrict__ out)
{
    __shared__ float hs[2][256];
    __shared__ float partial[128];
    __shared__ int   src_s[SEQT];
    __shared__ __align__(8) unsigned long long mbar[2];

    const int t  = threadIdx.x;
    const int w  = t >> 5;
    const int l  = t & 31;
    const int p  = w & 3;         // pair id
    const int kh = w >> 2;        // k-half this warp multiplies
    const int col = p * 32 + l;   // local output column 0..127
    const int k0  = kh * 128;
    const int b   = blockIdx.x >> 1;

    uint32_t rank;
    asm("mov.u32 %0, %%cluster_ctarank;" : "=r"(rank));

    const int  jout      = (int)rank * 128 + col;   // global output column
    const bool is_remote = (kh != (int)rank);       // warp-uniform

    for (int i = t; i < SEQT; i += 256) src_s[i] = source[b * SEQT + i];

    // W_hh[k0..k0+127][jout] register-resident as 64 f32x2
    unsigned long long wreg[64];
#pragma unroll
    for (int i = 0; i < 64; i++)
        wreg[i] = pack2(W_hh[(size_t)(k0 + 2 * i + 0) * HID + jout],
                        W_hh[(size_t)(k0 + 2 * i + 1) * HID + jout]);

    hs[0][t] = 0.0f;
    hs[1][t] = 0.0f;
    if (t == 0) {
        mbar_init(smem_u32(&mbar[0]), 1);
        mbar_init(smem_u32(&mbar[1]), 1);
        mbar_expect_tx(smem_u32(&mbar[0]), 512);  // pre-arm phase 0 of both
        mbar_expect_tx(smem_u32(&mbar[1]), 512);
    }

    uint32_t peer_h[2], peer_mbar[2], mbar_local[2];
    peer_h[0]    = mapa_peer(smem_u32(&hs[0][jout]), rank ^ 1u);
    peer_h[1]    = mapa_peer(smem_u32(&hs[1][jout]), rank ^ 1u);
    peer_mbar[0] = mapa_peer(smem_u32(&mbar[0]), rank ^ 1u);
    peer_mbar[1] = mapa_peer(smem_u32(&mbar[1]), rank ^ 1u);
    mbar_local[0] = smem_u32(&mbar[0]);
    mbar_local[1] = smem_u32(&mbar[1]);

    __syncthreads();
    CLUSTER_SYNC();  // mbar init + expect visible cluster-wide before any st.async

    float hval = 0.0f;

#pragma unroll 1
    for (int step = 0; step < SEQT; step++) {
        const int cur = step & 1;
        const int nxt = cur ^ 1;

        if (is_remote) {
            // Prefetch x-projection (LDS idx + L2 gather) — hides under wait+FMA
            float xv = g_V[(size_t)src_s[step] * HID + jout];

            if (step > 0) {
                mbar_wait_parity(mbar_local[cur], ((uint32_t)(step - 1) >> 1) & 1u);
                // Re-arm this mbar's next phase (filled 2 steps from now);
                // causality via the symmetric data dependency gives ~600cyc margin.
                if (p == 0 && l == 0) mbar_expect_tx(mbar_local[cur], 512);
            }

            const float* hp = &hs[cur][k0];
            unsigned long long a0 = 0, a1 = 0, a2 = 0, a3 = 0;
            unsigned long long b0 = 0, b1 = 0, b2 = 0, b3 = 0;
#pragma unroll
            for (int q = 0; q < 32; q += 4) {
                ulonglong2 h0 = *(const ulonglong2*)(hp + 4 * (q + 0));
                ulonglong2 h1 = *(const ulonglong2*)(hp + 4 * (q + 1));
                ulonglong2 h2 = *(const ulonglong2*)(hp + 4 * (q + 2));
                ulonglong2 h3 = *(const ulonglong2*)(hp + 4 * (q + 3));
                fma2(a0, h0.x, wreg[2 * q + 0]); fma2(b0, h0.y, wreg[2 * q + 1]);
                fma2(a1, h1.x, wreg[2 * q + 2]); fma2(b1, h1.y, wreg[2 * q + 3]);
                fma2(a2, h2.x, wreg[2 * q + 4]); fma2(b2, h2.y, wreg[2 * q + 5]);
                fma2(a3, h3.x, wreg[2 * q + 6]); fma2(b3, h3.y, wreg[2 * q + 7]);
            }
            unsigned long long s = add2(add2(add2(a0, a1), add2(a2, a3)),
                                        add2(add2(b0, b1), add2(b2, b3)));
            float lo, hi;
            unpack2(s, lo, hi);
            float pr = lo + hi;

            asm volatile("bar.sync %0, 64;" :: "r"(p + 1) : "memory");

            float pre = xv + pr + partial[col];
            float e = __expf(2.0f * pre);
            hval = 1.0f - __fdividef(2.0f, e + 1.0f);

            hs[nxt][jout] = hval;                              // local copy
            st_async_f32(peer_h[nxt], hval, peer_mbar[nxt]);   // data+signal fused
        } else {
            const float* hp = &hs[cur][k0];
            unsigned long long a0 = 0, a1 = 0, a2 = 0, a3 = 0;
            unsigned long long b0 = 0, b1 = 0, b2 = 0, b3 = 0;
#pragma unroll
            for (int q = 0; q < 32; q += 4) {
                ulonglong2 h0 = *(const ulonglong2*)(hp + 4 * (q + 0));
                ulonglong2 h1 = *(const ulonglong2*)(hp + 4 * (q + 1));
                ulonglong2 h2 = *(const ulonglong2*)(hp + 4 * (q + 2));
                ulonglong2 h3 = *(const ulonglong2*)(hp + 4 * (q + 3));
                fma2(a0, h0.x, wreg[2 * q + 0]); fma2(b0, h0.y, wreg[2 * q + 1]);
                fma2(a1, h1.x, wreg[2 * q + 2]); fma2(b1, h1.y, wreg[2 * q + 3]);
                fma2(a2, h2.x, wreg[2 * q + 4]); fma2(b2, h2.y, wreg[2 * q + 5]);
                fma2(a3, h3.x, wreg[2 * q + 6]); fma2(b3, h3.y, wreg[2 * q + 7]);
            }
            unsigned long long s = add2(add2(add2(a0, a1), add2(a2, a3)),
                                        add2(add2(b0, b1), add2(b2, b3)));
            float lo, hi;
            unpack2(s, lo, hi);
            partial[col] = lo + hi;

            asm volatile("bar.sync %0, 64;" :: "r"(p + 1) : "memory");
        }

        __syncthreads();  // local h stores visible; recycles partial[] + hs[nxt]
    }

    if (is_remote) out[b * HID + jout] = hval;

    CLUSTER_SYNC();  // keep peer SMEM alive for in-flight final st.asyncs
}

// ---------------------------------------------------------------------------
extern "C" void kernel_launch(void* const* d_in, const int* in_sizes, int n_in,
                              void* d_out, int out_size)
{
    const int*   source    = (const int*)d_in[0];
    const float* embedding = (const float*)d_in[1];
    const float* W_ih      = (const float*)d_in[2];
    const float* W_hh      = (const float*)d_in[3];
    const float* b_ih      = (const float*)d_in[4];
    const float* b_hh      = (const float*)d_in[5];
    float* out = (float*)d_out;

    vocab_proj_kernel<<<VOCAB / 64, 256>>>(embedding, W_ih, b_ih, b_hh);
    rnn_kernel<<<BATCH * 2, 256>>>(source, W_hh, out);
}